// round 3
// baseline (speedup 1.0000x reference)
#include <cuda_runtime.h>

// Problem constants: B=16, N=8192, C=128, H=2, hd=64, G=2
#define NB 16
#define NN 8192
#define TILE 64
#define NCH 128            // NN / TILE chunks per b

// Scratch (device globals — no allocation allowed)
__device__ float g_num[NB * 2 * NCH * 128];     // per-chunk Σ e·x   (2 MB)
__device__ float g_den[NB * 2 * NCH];           // per-chunk Σ e
__device__ float g_fv[NB * 2 * 128];            // final vectors [b][half][c]

// ---------------------------------------------------------------------------
// FUSED: u-precompute (per block, tiny) + logits + exp (no max shift; logits
// are O(1)) + weighted accumulation. One 64-row tile per block, smem-staged,
// zero warp shuffles, conflict-free LDS patterns.
// grid = NB*NCH = 2048 blocks x 256 threads.
// ---------------------------------------------------------------------------
__global__ __launch_bounds__(256) void k_fused(const float* __restrict__ x,
                                               const float* __restrict__ Wk,
                                               const float* __restrict__ mem) {
    __shared__ float  su[256];          // folded mem·Wk·scale
    __shared__ float4 xs[TILE][33];     // padded tile (stride 33 float4)
    __shared__ float  pd[2][TILE][4];   // partial dots [h][row][quarter]
    __shared__ float  se[2][TILE];      // exp values

    int t = threadIdx.x;

    // u[h, g*64+i] = scale * sum_j mem[h,2j+g] * Wk[g, h*32+j, i]
    {
        int h = t >> 7, cin = t & 127, g = cin >> 6, i = cin & 63;
        float acc = 0.f;
#pragma unroll
        for (int j = 0; j < 32; ++j)
            acc += mem[h * 64 + 2 * j + g] * Wk[(g * 64 + h * 32 + j) * 64 + i];
        su[t] = acc * 0.125f;           // scale = 1/8
    }

    int b = blockIdx.x >> 7;
    int chunk = blockIdx.x & (NCH - 1);
    const float4* xb = (const float4*)x + ((size_t)b * NN + (size_t)chunk * TILE) * 32;

    // Load tile: 2048 float4, coalesced, front-batched (MLP=8)
    float4 v[8];
#pragma unroll
    for (int k = 0; k < 8; ++k) v[k] = __ldg(xb + t + 256 * k);
#pragma unroll
    for (int k = 0; k < 8; ++k) {
        int idx = t + 256 * k;
        xs[idx >> 5][idx & 31] = v[k];
    }
    __syncthreads();

    // Phase A: dots. thread -> (row r = t/4, quarter q = t%4), 32 channels each.
    // Read order i=(s+2q)&7 makes each 8-lane LDS.128 phase hit 8 distinct
    // mod-8 bank groups (stride 33 ≡ 1 mod 8).
    {
        int r = t >> 2, q = t & 3;
        const float4* su4 = (const float4*)su;
        float p0 = 0.f, p1 = 0.f;
#pragma unroll
        for (int s = 0; s < 8; ++s) {
            int c = q * 8 + ((s + 2 * q) & 7);
            float4 xv = xs[r][c];
            float4 u0 = su4[c];
            float4 u1 = su4[32 + c];
            p0 += xv.x * u0.x + xv.y * u0.y + xv.z * u0.z + xv.w * u0.w;
            p1 += xv.x * u1.x + xv.y * u1.y + xv.z * u1.z + xv.w * u1.w;
        }
        pd[0][r][q] = p0;
        pd[1][r][q] = p1;
    }
    __syncthreads();

    // exp phase: 128 (h,row) pairs
    if (t < 128) {
        int h = t >> 6, r = t & 63;
        se[h][r] = __expf(pd[h][r][0] + pd[h][r][1] + pd[h][r][2] + pd[h][r][3]);
    }
    __syncthreads();

    // Phase B: weighted accumulate. thread -> (rowgroup rg = t/32, channel c4).
    // All lanes of a warp read the same row -> conflict-free LDS.128 + broadcast.
    int rg = t >> 5, c4 = t & 31;
    float4 a0 = make_float4(0.f, 0.f, 0.f, 0.f);
    float4 a1 = make_float4(0.f, 0.f, 0.f, 0.f);
#pragma unroll
    for (int k = 0; k < 8; ++k) {
        int r = rg * 8 + k;
        float4 xv = xs[r][c4];
        float e0 = se[0][r], e1 = se[1][r];
        a0.x += e0 * xv.x; a0.y += e0 * xv.y; a0.z += e0 * xv.z; a0.w += e0 * xv.w;
        a1.x += e1 * xv.x; a1.y += e1 * xv.y; a1.z += e1 * xv.z; a1.w += e1 * xv.w;
    }
    __syncthreads();                    // all xs reads done before aliasing

    // Cross-rowgroup reduce via smem (alias onto xs region, now dead)
    float4 (*sacc)[8][32] = (float4 (*)[8][32])xs;
    sacc[0][rg][c4] = a0;
    sacc[1][rg][c4] = a1;
    __syncthreads();

    if (t < 64) {
        int h = t >> 5, c = t & 31;
        float4 r = sacc[h][0][c];
#pragma unroll
        for (int g = 1; g < 8; ++g) {
            float4 q2 = sacc[h][g][c];
            r.x += q2.x; r.y += q2.y; r.z += q2.z; r.w += q2.w;
        }
        ((float4*)g_num)[((size_t)(b * 2 + h) * NCH + chunk) * 32 + c] = r;
    } else if (t < 66) {
        int h = t - 64;
        float d = 0.f;
#pragma unroll
        for (int r = 0; r < TILE; ++r) d += se[h][r];
        g_den[(size_t)(b * 2 + h) * NCH + chunk] = d;
    }
}

// ---------------------------------------------------------------------------
// Finalize. Per b: reduce chunk partials -> xa = num/den, row = xa·Wv
// (interleaved map), fv = row·Wp + bp. 16 blocks x 128 threads.
// ---------------------------------------------------------------------------
__global__ void k_final(const float* __restrict__ Wv, const float* __restrict__ Wp,
                        const float* __restrict__ bp) {
    int b = blockIdx.x;
    int t = threadIdx.x;   // 128
    __shared__ float xs[256];    // xa[h][c]
    __shared__ float row[128];   // row[h*64+d]

    float a0 = 0.f, a1 = 0.f;
#pragma unroll 8
    for (int ch = 0; ch < NCH; ++ch) {
        a0 += g_num[((size_t)(b * 2 + 0) * NCH + ch) * 128 + t];
        a1 += g_num[((size_t)(b * 2 + 1) * NCH + ch) * 128 + t];
    }
    float d0 = 0.f, d1 = 0.f;
#pragma unroll 8
    for (int ch = 0; ch < NCH; ++ch) {
        d0 += g_den[(size_t)(b * 2 + 0) * NCH + ch];
        d1 += g_den[(size_t)(b * 2 + 1) * NCH + ch];
    }
    xs[t] = a0 / d0;
    xs[128 + t] = a1 / d1;
    __syncthreads();

    {   // row[b,h,d] = sum_i xa[b,h,g*64+i] * Wv[g, h*32+d/2, i], g=d%2
        int h = t >> 6, d = t & 63;
        int g = d & 1;
        int o = h * 32 + (d >> 1);
        const float* w = Wv + (g * 64 + o) * 64;
        const float* xv = xs + h * 128 + g * 64;
        float acc = 0.f;
#pragma unroll
        for (int i = 0; i < 64; ++i) acc += xv[i] * w[i];
        row[t] = acc;
    }
    __syncthreads();

    {   // fv[b,half,c2] = bp[g2,o2] + sum_i row[half,i]*Wp[g2,o2,i]
        int c2 = t, g2 = c2 & 1, o2 = c2 >> 1;
        const float* w = Wp + (g2 * 64 + o2) * 64;
        float bias = bp[g2 * 64 + o2];
        float f0 = bias, f1 = bias;
#pragma unroll
        for (int i = 0; i < 64; ++i) {
            f0 += row[i] * w[i];
            f1 += row[64 + i] * w[i];
        }
        g_fv[(size_t)b * 256 + c2] = f0;          // half 0  (n < 4096)
        g_fv[(size_t)b * 256 + 128 + c2] = f1;    // half 1  (n >= 4096)
    }
}

// ---------------------------------------------------------------------------
// Broadcast fv over N. 1024 blocks x 256 threads, 16 coalesced STG.128 each;
// fv value held in a register (single LDG per thread).
// out region for (b,half) is contiguous: 4096 rows x 32 float4.
// ---------------------------------------------------------------------------
__global__ __launch_bounds__(256) void k_bcast(float4* __restrict__ out) {
    int t = threadIdx.x;
    int bh = blockIdx.x >> 5;          // b*2 + half  (0..31)
    int seg = blockIdx.x & 31;         // 32 segments of 4096 float4
    float4 v = __ldg((const float4*)g_fv + (size_t)bh * 32 + (t & 31));
    float4* dst = out + (size_t)bh * 131072 + (size_t)seg * 4096;
#pragma unroll
    for (int k = 0; k < 16; ++k)
        dst[k * 256 + t] = v;          // (k*256+t) % 32 == t%32 -> channel match
}

// ---------------------------------------------------------------------------
extern "C" void kernel_launch(void* const* d_in, const int* in_sizes, int n_in,
                              void* d_out, int out_size) {
    const float* x   = (const float*)d_in[0];
    const float* Wk  = (const float*)d_in[1];
    const float* Wv  = (const float*)d_in[2];
    const float* Wp  = (const float*)d_in[3];
    const float* bp  = (const float*)d_in[4];
    const float* mem = (const float*)d_in[5];
    float* out = (float*)d_out;

    k_fused<<<NB * NCH, 256>>>(x, Wk, mem);
    k_final<<<NB, 128>>>(Wv, Wp, bp);
    k_bcast<<<1024, 256>>>((float4*)out);
}

// round 4
// speedup vs baseline: 1.2761x; 1.2761x over previous
#include <cuda_runtime.h>

// Problem constants: B=16, N=8192, C=128, H=2, hd=64, G=2
#define NB 16
#define NN 8192
#define TILE 32
#define NCH 256            // NN / TILE chunks per b

// Scratch (device globals — no allocation allowed)
__device__ float g_u[2 * 128];                  // folded mem·Wk·scale  [h][cin]
__device__ float g_num[NB * 2 * NCH * 128];     // per-chunk Σ e·x   (4 MB)
__device__ float g_den[NB * 2 * NCH];           // per-chunk Σ e
__device__ float g_fv[NB * 2 * 128];            // final vectors [b][half][c]

// ---------------------------------------------------------------------------
// Kernel 1: u[h, g*64+i] = scale * sum_j mem[h, 2j+g] * Wk[g, h*32+j, i]
// ---------------------------------------------------------------------------
__global__ void k_prep_u(const float* __restrict__ Wk, const float* __restrict__ mem) {
    int t = threadIdx.x;            // 256 threads: h = t/128, cin = t%128
    int h = t >> 7;
    int cin = t & 127;
    int g = cin >> 6;
    int i = cin & 63;
    float acc = 0.f;
#pragma unroll
    for (int j = 0; j < 32; ++j)
        acc += mem[h * 64 + 2 * j + g] * Wk[(g * 64 + h * 32 + j) * 64 + i];
    g_u[t] = acc * 0.125f;          // scale = hd^-0.5 = 1/8
}

// ---------------------------------------------------------------------------
// Kernel 2 (FUSED): logits + exp (no max shift; logits are O(1)) + weighted
// accumulation. 32-row tile per block, 128 threads (4 warps), each warp owns
// 8 rows end-to-end: registers for the data, smem only for the cross-lane
// dot, quad shuffles for reduction. ONE __syncthreads before the tail reduce
// (plus one for u staging). grid = NB*NCH = 4096 blocks.
// ---------------------------------------------------------------------------
__global__ __launch_bounds__(128) void k_fused(const float* __restrict__ x) {
    __shared__ float  su[256];          // folded u
    __shared__ float4 xs[TILE][33];     // padded tile (stride 33 float4)
    __shared__ float4 sacc[2][4][32];   // per-warp partial sums
    __shared__ float  sden[2][4];

    int t = threadIdx.x;
    int w = t >> 5, lane = t & 31;

    int b = blockIdx.x >> 8;
    int chunk = blockIdx.x & (NCH - 1);

    // Load tile: warp w owns rows 8w..8w+7; 8 coalesced LDG.128 per lane.
    const float4* xb = (const float4*)x
        + ((size_t)b * NN + (size_t)chunk * TILE + (size_t)w * 8) * 32 + lane;
    float4 v[8];
#pragma unroll
    for (int k = 0; k < 8; ++k) v[k] = __ldg(xb + k * 32);

    // Stage u + tile into smem
    su[t] = g_u[t];
    su[t + 128] = g_u[t + 128];
#pragma unroll
    for (int k = 0; k < 8; ++k) xs[w * 8 + k][lane] = v[k];
    __syncthreads();                    // su (cross-warp) + xs visibility

    // Phase A: dots. Quad layout: rl = lane/4 (row within warp), q = lane%4
    // (channel quarter). Column order (s+2q)&7 keeps every 8-lane LDS phase
    // on 8 distinct bank groups (stride 33 ≡ 1 mod 8).
    int rl = lane >> 2, q = lane & 3;
    const float4* su4 = (const float4*)su;
    float p0 = 0.f, p1 = 0.f;
#pragma unroll
    for (int s = 0; s < 8; ++s) {
        int c = q * 8 + ((s + 2 * q) & 7);
        float4 xv = xs[w * 8 + rl][c];
        float4 u0 = su4[c];
        float4 u1 = su4[32 + c];
        p0 += xv.x * u0.x + xv.y * u0.y + xv.z * u0.z + xv.w * u0.w;
        p1 += xv.x * u1.x + xv.y * u1.y + xv.z * u1.z + xv.w * u1.w;
    }
    // combine the 4 quarters (lanes 4rl..4rl+3)
    p0 += __shfl_xor_sync(0xffffffffu, p0, 1);
    p0 += __shfl_xor_sync(0xffffffffu, p0, 2);
    p1 += __shfl_xor_sync(0xffffffffu, p1, 1);
    p1 += __shfl_xor_sync(0xffffffffu, p1, 2);
    float e0 = __expf(p0);              // exp of row rl's logit (all 4 lanes)
    float e1 = __expf(p1);

    // Phase B: weighted accumulate from REGISTERS. v[k] = row 8w+k, channel
    // lane — exactly the element needed. e for row k lives in lanes 4k..4k+3.
    float4 a0 = make_float4(0.f, 0.f, 0.f, 0.f);
    float4 a1 = make_float4(0.f, 0.f, 0.f, 0.f);
    float den0 = 0.f, den1 = 0.f;
#pragma unroll
    for (int k = 0; k < 8; ++k) {
        float f0 = __shfl_sync(0xffffffffu, e0, k * 4);
        float f1 = __shfl_sync(0xffffffffu, e1, k * 4);
        a0.x += f0 * v[k].x; a0.y += f0 * v[k].y; a0.z += f0 * v[k].z; a0.w += f0 * v[k].w;
        a1.x += f1 * v[k].x; a1.y += f1 * v[k].y; a1.z += f1 * v[k].z; a1.w += f1 * v[k].w;
        den0 += f0; den1 += f1;
    }

    sacc[0][w][lane] = a0;
    sacc[1][w][lane] = a1;
    if (lane == 0) { sden[0][w] = den0; sden[1][w] = den1; }
    __syncthreads();

    if (t < 64) {
        int h = t >> 5, c = t & 31;
        float4 r = sacc[h][0][c];
#pragma unroll
        for (int ww = 1; ww < 4; ++ww) {
            float4 p = sacc[h][ww][c];
            r.x += p.x; r.y += p.y; r.z += p.z; r.w += p.w;
        }
        ((float4*)g_num)[((size_t)(b * 2 + h) * NCH + chunk) * 32 + c] = r;
    } else if (t < 66) {
        int h = t - 64;
        g_den[(size_t)(b * 2 + h) * NCH + chunk]
            = sden[h][0] + sden[h][1] + sden[h][2] + sden[h][3];
    }
}

// ---------------------------------------------------------------------------
// Kernel 3: finalize. One block per (b,h) — independent through Wp since the
// un-permuted reshape makes fv[b,half] depend only on head h=half.
// 32 blocks x 1024 threads: wide parallel chunk reduce, then tiny GEMV chain.
// ---------------------------------------------------------------------------
__global__ __launch_bounds__(1024) void k_final(const float* __restrict__ Wv,
                                                const float* __restrict__ Wp,
                                                const float* __restrict__ bp) {
    int bh = blockIdx.x, b = bh >> 1, h = bh & 1;
    int t = threadIdx.x;
    __shared__ float sred[8][128];
    __shared__ float sdn[8];
    __shared__ float xa[128];
    __shared__ float row[64];

    int c = t & 127, slice = t >> 7;    // 8 slices x 32 chunks
    const float* base = g_num + (size_t)bh * NCH * 128;
    float a = 0.f;
#pragma unroll
    for (int j = 0; j < 32; ++j)
        a += base[(size_t)(slice * 32 + j) * 128 + c];
    sred[slice][c] = a;

    if (t < 256) {                       // den reduce: 8 full warps
        float d = g_den[(size_t)bh * NCH + t];
#pragma unroll
        for (int off = 16; off > 0; off >>= 1)
            d += __shfl_xor_sync(0xffffffffu, d, off);
        if ((t & 31) == 0) sdn[t >> 5] = d;
    }
    __syncthreads();

    if (t < 128) {
        float s = 0.f;
#pragma unroll
        for (int sl = 0; sl < 8; ++sl) s += sred[sl][t];
        float dd = sdn[0] + sdn[1] + sdn[2] + sdn[3]
                 + sdn[4] + sdn[5] + sdn[6] + sdn[7];
        xa[t] = s / dd;
    }
    __syncthreads();

    if (t < 64) {                        // row[d] = sum_i xa[g*64+i]*Wv[g,h*32+d/2,i]
        int g = t & 1, o = h * 32 + (t >> 1);
        const float* w = Wv + (g * 64 + o) * 64;
        const float* xv = xa + g * 64;
        float acc = 0.f;
#pragma unroll
        for (int i = 0; i < 64; ++i) acc += xv[i] * w[i];
        row[t] = acc;
    }
    __syncthreads();

    if (t < 128) {                       // fv = row·Wp + bp (half == h)
        int g2 = t & 1, o2 = t >> 1;
        const float* w = Wp + (g2 * 64 + o2) * 64;
        float f = bp[g2 * 64 + o2];
#pragma unroll
        for (int i = 0; i < 64; ++i) f += row[i] * w[i];
        g_fv[(size_t)b * 256 + h * 128 + t] = f;
    }
}

// ---------------------------------------------------------------------------
// Kernel 4: broadcast fv over N. 1024 blocks x 256 threads, fv in a register,
// 16 coalesced STG.128 each. out region for (b,half) contiguous: 4096x32 f4.
// ---------------------------------------------------------------------------
__global__ __launch_bounds__(256) void k_bcast(float4* __restrict__ out) {
    int t = threadIdx.x;
    int bh = blockIdx.x >> 5;          // b*2 + half  (0..31)
    int seg = blockIdx.x & 31;         // 32 segments of 4096 float4
    float4 v = __ldg((const float4*)g_fv + (size_t)bh * 32 + (t & 31));
    float4* dst = out + (size_t)bh * 131072 + (size_t)seg * 4096;
#pragma unroll
    for (int k = 0; k < 16; ++k)
        dst[k * 256 + t] = v;          // channel (addr%32) matches t%32
}

// ---------------------------------------------------------------------------
extern "C" void kernel_launch(void* const* d_in, const int* in_sizes, int n_in,
                              void* d_out, int out_size) {
    const float* x   = (const float*)d_in[0];
    const float* Wk  = (const float*)d_in[1];
    const float* Wv  = (const float*)d_in[2];
    const float* Wp  = (const float*)d_in[3];
    const float* bp  = (const float*)d_in[4];
    const float* mem = (const float*)d_in[5];
    float* out = (float*)d_out;

    k_prep_u<<<1, 256>>>(Wk, mem);
    k_fused<<<NB * NCH, 128>>>(x);
    k_final<<<32, 1024>>>(Wv, Wp, bp);
    k_bcast<<<1024, 256>>>((float4*)out);
}

// round 5
// speedup vs baseline: 1.2779x; 1.0015x over previous
#include <cuda_runtime.h>

// Problem constants: B=16, N=8192, C=128, H=2, hd=64, G=2
#define NB 16
#define NN 8192
#define TILE 32
#define TPB 256            // 32-row tiles per b
#define P 768              // persistent blocks (148 SMs x 6 capacity = 888 >= 768)
#define BPB 48             // blocks per b

// Scratch (device globals — no allocation allowed; zero-initialized)
__device__ float g_num[32 * BPB * 128];     // per-block partial Σ e·x
__device__ float g_den[32 * BPB];           // per-block partial Σ e
__device__ float g_fv[NB * 2 * 128];        // final vectors [b][half][c]
__device__ unsigned g_cnt[2];               // barrier counters (reset each use)
__device__ unsigned g_epoch[2];             // barrier epochs (monotonic)

// Grid barrier: epoch snapshot + count. Counter returns to 0 after each use,
// epoch only grows -> identical behavior on every graph replay.
// Caller must __threadfence() (all threads) BEFORE if it published data.
__device__ __forceinline__ void gbar(int id, bool wait_flag) {
    __syncthreads();
    if (threadIdx.x == 0) {
        unsigned e0 = *((volatile unsigned*)&g_epoch[id]);
        unsigned prev = atomicAdd(&g_cnt[id], 1u);
        if (prev == (unsigned)gridDim.x - 1u) {
            atomicExch(&g_cnt[id], 0u);
            __threadfence();
            atomicAdd(&g_epoch[id], 1u);
        } else if (wait_flag) {
            while (*((volatile unsigned*)&g_epoch[id]) == e0) __nanosleep(64);
            __threadfence();
        }
    }
    __syncthreads();
}

__global__ __launch_bounds__(128, 6) void k_all(
    const float* __restrict__ x,  const float* __restrict__ Wk,
    const float* __restrict__ Wv, const float* __restrict__ Wp,
    const float* __restrict__ bp, const float* __restrict__ mem,
    float4* __restrict__ out)
{
    __shared__ float  su[256];          // folded mem·Wk·scale
    __shared__ float4 xs[TILE][33];     // padded tile (warp-private rows)
    __shared__ float4 sacc[2][4][32];
    __shared__ float  sden[2][4];
    __shared__ float  xa[128];
    __shared__ float  rowv[64];
    __shared__ float  sd48[BPB];

    int t = threadIdx.x, w = t >> 5, lane = t & 31;

    // ---- u precompute (per block; Wk/mem are tiny and L2-hot) ----
#pragma unroll
    for (int rep = 0; rep < 2; ++rep) {
        int tt = t + rep * 128;
        int h = tt >> 7, cin = tt & 127, g = cin >> 6, i = cin & 63;
        float acc = 0.f;
#pragma unroll
        for (int j = 0; j < 32; ++j)
            acc += mem[h * 64 + 2 * j + g] * Wk[(g * 64 + h * 32 + j) * 64 + i];
        su[tt] = acc * 0.125f;          // scale = hd^-0.5 = 1/8
    }
    __syncthreads();

    // ---- Phase 1: fused logits + exp + weighted accumulate over own tiles ----
    int b = blockIdx.x / BPB;
    int l = blockIdx.x % BPB;
    int tile0 = (l * TPB) / BPB;
    int tile1 = ((l + 1) * TPB) / BPB;

    int rl = lane >> 2, q = lane & 3;
    const float4* su4 = (const float4*)su;

    float4 a0 = make_float4(0.f, 0.f, 0.f, 0.f);
    float4 a1 = make_float4(0.f, 0.f, 0.f, 0.f);
    float den0 = 0.f, den1 = 0.f;

    for (int tile = tile0; tile < tile1; ++tile) {
        const float4* xb = (const float4*)x
            + ((size_t)b * NN + (size_t)tile * TILE + (size_t)w * 8) * 32 + lane;
        float4 v[8];
#pragma unroll
        for (int k = 0; k < 8; ++k) v[k] = __ldcs(xb + k * 32);

        __syncwarp();                   // prior iter's xs reads done
#pragma unroll
        for (int k = 0; k < 8; ++k) xs[w * 8 + k][lane] = v[k];
        __syncwarp();                   // xs writes visible within warp

        // dots: rl = row within warp, q = channel quarter; column order
        // (s+2q)&7 keeps 8-lane LDS phases on distinct bank groups.
        float p0 = 0.f, p1 = 0.f;
#pragma unroll
        for (int s = 0; s < 8; ++s) {
            int c = q * 8 + ((s + 2 * q) & 7);
            float4 xv = xs[w * 8 + rl][c];
            float4 u0 = su4[c];
            float4 u1 = su4[32 + c];
            p0 += xv.x * u0.x + xv.y * u0.y + xv.z * u0.z + xv.w * u0.w;
            p1 += xv.x * u1.x + xv.y * u1.y + xv.z * u1.z + xv.w * u1.w;
        }
        p0 += __shfl_xor_sync(0xffffffffu, p0, 1);
        p0 += __shfl_xor_sync(0xffffffffu, p0, 2);
        p1 += __shfl_xor_sync(0xffffffffu, p1, 1);
        p1 += __shfl_xor_sync(0xffffffffu, p1, 2);
        float e0 = __expf(p0);          // exp of row rl's logit (no max shift;
        float e1 = __expf(p1);          // logits are O(1) by construction)

#pragma unroll
        for (int k = 0; k < 8; ++k) {
            float f0 = __shfl_sync(0xffffffffu, e0, k * 4);
            float f1 = __shfl_sync(0xffffffffu, e1, k * 4);
            a0.x += f0 * v[k].x; a0.y += f0 * v[k].y; a0.z += f0 * v[k].z; a0.w += f0 * v[k].w;
            a1.x += f1 * v[k].x; a1.y += f1 * v[k].y; a1.z += f1 * v[k].z; a1.w += f1 * v[k].w;
            den0 += f0; den1 += f1;
        }
    }

    // block combine -> one partial per (b,h,l)
    sacc[0][w][lane] = a0;
    sacc[1][w][lane] = a1;
    if (lane == 0) { sden[0][w] = den0; sden[1][w] = den1; }
    __syncthreads();

    if (t < 64) {
        int h = t >> 5, c = t & 31;
        float4 r = sacc[h][0][c];
#pragma unroll
        for (int ww = 1; ww < 4; ++ww) {
            float4 p = sacc[h][ww][c];
            r.x += p.x; r.y += p.y; r.z += p.z; r.w += p.w;
        }
        ((float4*)g_num)[((size_t)(b * 2 + h) * BPB + l) * 32 + c] = r;
    } else if (t < 66) {
        int h = t - 64;
        g_den[(size_t)(b * 2 + h) * BPB + l]
            = sden[h][0] + sden[h][1] + sden[h][2] + sden[h][3];
    }
    __threadfence();                    // publish partials
    gbar(0, blockIdx.x < 32);

    // ---- Phase 2: finalize (blocks 0..31, one per (b,h)) ----
    if (blockIdx.x < 32) {
        int bh = blockIdx.x;
        int h = bh & 1;
        const float* basep = g_num + (size_t)bh * BPB * 128;
        float a = 0.f;
#pragma unroll
        for (int j = 0; j < BPB; ++j) a += basep[(size_t)j * 128 + t];
        if (t < BPB) sd48[t] = g_den[(size_t)bh * BPB + t];
        __syncthreads();
        float d = 0.f;
#pragma unroll
        for (int j = 0; j < BPB; ++j) d += sd48[j];   // broadcast LDS
        xa[t] = a / d;
        __syncthreads();

        if (t < 64) {                   // row[d] = Σ_i xa[g*64+i]·Wv[g,h*32+d/2,i]
            int g = t & 1, o = h * 32 + (t >> 1);
            const float* wv = Wv + (g * 64 + o) * 64;
            const float* xv = xa + g * 64;
            float acc = 0.f;
#pragma unroll
            for (int i = 0; i < 64; ++i) acc += xv[i] * wv[i];
            rowv[t] = acc;
        }
        __syncthreads();

        {                               // fv = row·Wp + bp (half == h)
            int g2 = t & 1, o2 = t >> 1;
            const float* wp = Wp + (g2 * 64 + o2) * 64;
            float f = bp[g2 * 64 + o2];
#pragma unroll
            for (int i = 0; i < 64; ++i) f += rowv[i] * wp[i];
            g_fv[(size_t)(bh >> 1) * 256 + h * 128 + t] = f;
        }
        __threadfence();                // publish fv
    }
    gbar(1, true);

    // ---- Phase 3: broadcast. out[b,n,c] = fv[b, n>=4096, c]; 64MB streamed ----
    const float4* fv4 = (const float4*)g_fv;
    unsigned stride = P * 128u;
    for (unsigned idx = blockIdx.x * 128u + t; idx < 4194304u; idx += stride) {
        unsigned bh = idx >> 17;        // 131072 float4 per (b,half) region
        float4 vv = __ldg(fv4 + bh * 32 + (idx & 31));
        __stcs(out + idx, vv);
    }
}

// ---------------------------------------------------------------------------
extern "C" void kernel_launch(void* const* d_in, const int* in_sizes, int n_in,
                              void* d_out, int out_size) {
    const float* x   = (const float*)d_in[0];
    const float* Wk  = (const float*)d_in[1];
    const float* Wv  = (const float*)d_in[2];
    const float* Wp  = (const float*)d_in[3];
    const float* bp  = (const float*)d_in[4];
    const float* mem = (const float*)d_in[5];
    float4* out = (float4*)d_out;

    k_all<<<P, 128>>>(x, Wk, Wv, Wp, bp, mem, out);
}